// round 5
// baseline (speedup 1.0000x reference)
#include <cuda_runtime.h>

#define NB 16
#define NC 64
#define NH 128
#define NW 128
#define NE 8
#define NGH 16

typedef unsigned long long ull;

__device__ float g_pooled[NB * NC];
__device__ float g_probs[NB][NE];
__device__ float g_wcomb[NB * NC * NC * 9];
__device__ float g_bcomb[NB][NC];

#define PACK2(d, lo, hi) \
    asm("mov.b64 %0, {%1, %2};" : "=l"(d) : "f"(lo), "f"(hi))
#define UNPACK2(lo, hi, d) \
    asm("mov.b64 {%0, %1}, %2;" : "=f"(lo), "=f"(hi) : "l"(d))
#define FMA2(d, a, b) \
    asm("fma.rn.f32x2 %0, %1, %2, %0;" : "+l"(d) : "l"(a), "l"(b))

// ---------------------------------------------------------------------------
// Kernel 1a: parallel GAP. One block per (b, c): 1024 blocks.
// ---------------------------------------------------------------------------
__global__ __launch_bounds__(256)
void pool_kernel(const float* __restrict__ x) {
    const int bc = blockIdx.x;
    const int tid = threadIdx.x;
    const float4* p4 = (const float4*)(x + (size_t)bc * NH * NW);

    float s = 0.f;
    #pragma unroll 4
    for (int i = tid; i < (NH * NW) / 4; i += 256) {
        float4 v = p4[i];
        s += (v.x + v.y) + (v.z + v.w);
    }
    #pragma unroll
    for (int o = 16; o > 0; o >>= 1) s += __shfl_xor_sync(0xffffffffu, s, o);

    __shared__ float ws[8];
    if ((tid & 31) == 0) ws[tid >> 5] = s;
    __syncthreads();
    if (tid == 0) {
        float t = 0.f;
        #pragma unroll
        for (int w = 0; w < 8; w++) t += ws[w];
        g_pooled[bc] = t * (1.0f / (NH * NW));
    }
}

// ---------------------------------------------------------------------------
// Kernel 1b: gating MLP + softmax + top-2. One block per batch (tiny).
// ---------------------------------------------------------------------------
__global__ void gate_kernel(const float* __restrict__ wg1,
                            const float* __restrict__ bg1,
                            const float* __restrict__ wg2,
                            const float* __restrict__ bg2) {
    const int b = blockIdx.x;
    const int tid = threadIdx.x;  // 64 threads

    __shared__ float pooled[NC];
    __shared__ float hbuf[NGH];
    __shared__ float logits[NE];

    if (tid < NC) pooled[tid] = g_pooled[b * NC + tid];
    __syncthreads();

    if (tid < NGH) {
        float a = bg1[tid];
        #pragma unroll
        for (int c = 0; c < NC; c++) a += pooled[c] * wg1[c * NGH + tid];
        hbuf[tid] = a > 0.f ? a : 0.f;
    }
    __syncthreads();

    if (tid < NE) {
        float a = bg2[tid];
        #pragma unroll
        for (int g = 0; g < NGH; g++) a += hbuf[g] * wg2[g * NE + tid];
        logits[tid] = a;
    }
    __syncthreads();

    if (tid == 0) {
        float m = -1e30f;
        #pragma unroll
        for (int e = 0; e < NE; e++) m = fmaxf(m, logits[e]);
        float p[NE], s = 0.f;
        #pragma unroll
        for (int e = 0; e < NE; e++) { p[e] = expf(logits[e] - m); s += p[e]; }
        float inv = 1.0f / s;
        #pragma unroll
        for (int e = 0; e < NE; e++) p[e] *= inv;
        int i1 = 0;
        #pragma unroll
        for (int e = 1; e < NE; e++) if (p[e] > p[i1]) i1 = e;
        int i2 = -1;
        #pragma unroll
        for (int e = 0; e < NE; e++) {
            if (e == i1) continue;
            if (i2 < 0 || p[e] > p[i2]) i2 = e;
        }
        float denom = p[i1] + p[i2] + 1e-8f;
        #pragma unroll
        for (int e = 0; e < NE; e++)
            g_probs[b][e] = (e == i1 || e == i2) ? p[e] / denom : 0.f;
    }
}

// ---------------------------------------------------------------------------
// Kernel 2: fold routing probs into per-batch conv weights + bias.
// ---------------------------------------------------------------------------
__global__ void combine_kernel(const float* __restrict__ w_exp,
                               const float* __restrict__ b_exp) {
    const int idx = blockIdx.x * blockDim.x + threadIdx.x;
    const int total = NB * NC * NC * 9;
    if (idx < total) {
        const int b = idx / (NC * NC * 9);
        const int r = idx - b * (NC * NC * 9);   // co*(NC*9) + ci*9 + tap
        const int co = r / (NC * 9);
        const int r2 = r - co * (NC * 9);        // ci*9 + tap
        float s = 0.f;
        #pragma unroll
        for (int e = 0; e < NE; e++)
            s += g_probs[b][e] * w_exp[((size_t)(e * NC + co) * NC) * 9 + r2];
        g_wcomb[idx] = s;
    }
    if (idx < NB * NC) {
        const int b = idx / NC, c = idx - b * NC;
        float s = 0.f;
        #pragma unroll
        for (int e = 0; e < NE; e++) s += g_probs[b][e] * b_exp[e * NC + c];
        g_bcomb[b][c] = s;
    }
}

// ---------------------------------------------------------------------------
// Kernel 3: per-batch 3x3 SAME conv, fused bias + residual, f32x2 FMA.
// Tile 32(w) x 64(h). Block 256 = 8(px) x 32(py); each thread: 4(dx) x 2(dy)
// outputs for 8 c_out -> 64 outputs, 32 packed f32x2 accumulators.
// Grid: (8 tiles, 8 cog, 16 b).
// ---------------------------------------------------------------------------
#define TCI 4
#define TCO 8

__global__ __launch_bounds__(256, 2)
void conv_kernel(const float* __restrict__ x, float* __restrict__ out) {
    const int tile = blockIdx.x;          // 0..7: 4 x-tiles, 2 y-tiles
    const int cog  = blockIdx.y;          // 0..7
    const int b    = blockIdx.z;          // 0..15
    const int tx = tile & 3, tyi = tile >> 2;
    const int X0 = tx * 32, Y0 = tyi * 64;

    const int tid = threadIdx.x;
    const int px = tid & 7, py = tid >> 3;   // 8 x 32

    __shared__ float  in_s[TCI][66][36];     // 66 rows (64+2 halo), stride 144B
    __shared__ float2 w2_s[TCO][TCI][9];     // duplicated weights {w,w}

    ull acc2[TCO][2][2];                     // [co][dy][pair g]
    #pragma unroll
    for (int co = 0; co < TCO; co++)
        #pragma unroll
        for (int dy = 0; dy < 2; dy++) {
            acc2[co][dy][0] = 0ull;
            acc2[co][dy][1] = 0ull;
        }

    const float* xb = x + (size_t)b * NC * NH * NW;
    const float* wb = g_wcomb + (size_t)b * NC * NC * 9;

    for (int cb = 0; cb < NC / TCI; cb++) {
        __syncthreads();
        // stage input: TCI channels x 66x34 (zero-padded halo)
        for (int i = tid; i < TCI * 66 * 34; i += 256) {
            const int ci = i / (66 * 34);
            const int rr = i - ci * (66 * 34);
            const int iy = rr / 34, ix = rr - iy * 34;
            const int gy = Y0 - 1 + iy;
            const int gx = X0 - 1 + ix;
            float v = 0.f;
            if (gy >= 0 && gy < NH && gx >= 0 && gx < NW)
                v = xb[((size_t)(cb * TCI + ci) * NH + gy) * NW + gx];
            in_s[ci][iy][ix] = v;
        }
        // stage duplicated weights: TCO x TCI x 9 = 288 elements (> 256
        // threads, so this MUST be a grid-stride loop)
        for (int i = tid; i < TCO * TCI * 9; i += 256) {
            const int co = i / (TCI * 9);
            const int r  = i - co * (TCI * 9);
            const int ci = r / 9, tap = r - ci * 9;
            const float v =
                wb[((size_t)(cog * TCO + co) * NC + cb * TCI + ci) * 9 + tap];
            w2_s[co][ci][tap] = make_float2(v, v);
        }
        __syncthreads();

        #pragma unroll 1
        for (int ci = 0; ci < TCI; ci++) {
            // 4 rows x 6 cols window -> even pairs E[r][0..2], odd O[r][0..1]
            ull E[4][3], O[4][2];
            #pragma unroll
            for (int r = 0; r < 4; r++) {
                const float* row = &in_s[ci][py * 2 + r][px * 4];
                const float4 a = *(const float4*)row;
                const float2 bvec = *(const float2*)(row + 4);
                PACK2(E[r][0], a.x, a.y);
                PACK2(E[r][1], a.z, a.w);
                PACK2(E[r][2], bvec.x, bvec.y);
                PACK2(O[r][0], a.y, a.z);
                PACK2(O[r][1], a.w, bvec.x);
            }

            #pragma unroll
            for (int co = 0; co < TCO; co++) {
                const ull* wp = (const ull*)&w2_s[co][ci][0];
                #pragma unroll
                for (int ky = 0; ky < 3; ky++) {
                    const ull w0 = wp[ky * 3 + 0];
                    FMA2(acc2[co][0][0], E[ky    ][0], w0);
                    FMA2(acc2[co][0][1], E[ky    ][1], w0);
                    FMA2(acc2[co][1][0], E[ky + 1][0], w0);
                    FMA2(acc2[co][1][1], E[ky + 1][1], w0);
                    const ull w1 = wp[ky * 3 + 1];
                    FMA2(acc2[co][0][0], O[ky    ][0], w1);
                    FMA2(acc2[co][0][1], O[ky    ][1], w1);
                    FMA2(acc2[co][1][0], O[ky + 1][0], w1);
                    FMA2(acc2[co][1][1], O[ky + 1][1], w1);
                    const ull w2 = wp[ky * 3 + 2];
                    FMA2(acc2[co][0][0], E[ky    ][1], w2);
                    FMA2(acc2[co][0][1], E[ky    ][2], w2);
                    FMA2(acc2[co][1][0], E[ky + 1][1], w2);
                    FMA2(acc2[co][1][1], E[ky + 1][2], w2);
                }
            }
        }
    }

    // epilogue: bias + residual, float4 stores
    const int oy0 = Y0 + py * 2;
    const int ox0 = X0 + px * 4;
    #pragma unroll
    for (int co = 0; co < TCO; co++) {
        const int cg = cog * TCO + co;
        const float bias = g_bcomb[b][cg];
        #pragma unroll
        for (int dy = 0; dy < 2; dy++) {
            const size_t o = ((size_t)(b * NC + cg) * NH + (oy0 + dy)) * NW + ox0;
            float a0, a1, a2, a3;
            UNPACK2(a0, a1, acc2[co][dy][0]);
            UNPACK2(a2, a3, acc2[co][dy][1]);
            const float4 res = *(const float4*)(x + o);
            float4 v;
            v.x = a0 + bias + res.x;
            v.y = a1 + bias + res.y;
            v.z = a2 + bias + res.z;
            v.w = a3 + bias + res.w;
            *(float4*)(out + o) = v;
        }
    }
}

extern "C" void kernel_launch(void* const* d_in, const int* in_sizes, int n_in,
                              void* d_out, int out_size) {
    const float* x     = (const float*)d_in[0];
    const float* wg1   = (const float*)d_in[1];
    const float* bg1   = (const float*)d_in[2];
    const float* wg2   = (const float*)d_in[3];
    const float* bg2   = (const float*)d_in[4];
    const float* w_exp = (const float*)d_in[5];
    const float* b_exp = (const float*)d_in[6];
    float* out = (float*)d_out;

    pool_kernel<<<NB * NC, 256>>>(x);
    gate_kernel<<<NB, 64>>>(wg1, bg1, wg2, bg2);

    const int total = NB * NC * NC * 9;
    combine_kernel<<<(total + 255) / 256, 256>>>(w_exp, b_exp);

    dim3 grid(8, NC / TCO, NB);
    conv_kernel<<<grid, 256>>>(x, out);
}

// round 7
// speedup vs baseline: 1.5943x; 1.5943x over previous
#include <cuda_runtime.h>

#define NB 16
#define NC 64
#define NH 128
#define NW 128
#define NE 8
#define NGH 16

typedef unsigned long long ull;

__device__ float g_pooled[NB * NC];
__device__ float g_probs[NB][NE];
__device__ float g_wcomb[NB * NC * NC * 9];
__device__ float g_bcomb[NB][NC];

#define PACK2(d, lo, hi) \
    asm("mov.b64 %0, {%1, %2};" : "=l"(d) : "f"(lo), "f"(hi))
#define UNPACK2(lo, hi, d) \
    asm("mov.b64 {%0, %1}, %2;" : "=f"(lo), "=f"(hi) : "l"(d))
#define FMA2(d, a, b) \
    asm("fma.rn.f32x2 %0, %1, %2, %0;" : "+l"(d) : "l"(a), "l"(b))

// ---------------------------------------------------------------------------
// Kernel 1a: parallel GAP. One block per (b, c): 1024 blocks.
// ---------------------------------------------------------------------------
__global__ __launch_bounds__(256)
void pool_kernel(const float* __restrict__ x) {
    const int bc = blockIdx.x;
    const int tid = threadIdx.x;
    const float4* p4 = (const float4*)(x + (size_t)bc * NH * NW);

    float s = 0.f;
    #pragma unroll 4
    for (int i = tid; i < (NH * NW) / 4; i += 256) {
        float4 v = p4[i];
        s += (v.x + v.y) + (v.z + v.w);
    }
    #pragma unroll
    for (int o = 16; o > 0; o >>= 1) s += __shfl_xor_sync(0xffffffffu, s, o);

    __shared__ float ws[8];
    if ((tid & 31) == 0) ws[tid >> 5] = s;
    __syncthreads();
    if (tid == 0) {
        float t = 0.f;
        #pragma unroll
        for (int w = 0; w < 8; w++) t += ws[w];
        g_pooled[bc] = t * (1.0f / (NH * NW));
    }
}

// ---------------------------------------------------------------------------
// Kernel 1b: gating MLP + softmax + top-2. One block per batch (tiny).
// ---------------------------------------------------------------------------
__global__ void gate_kernel(const float* __restrict__ wg1,
                            const float* __restrict__ bg1,
                            const float* __restrict__ wg2,
                            const float* __restrict__ bg2) {
    const int b = blockIdx.x;
    const int tid = threadIdx.x;  // 64 threads

    __shared__ float pooled[NC];
    __shared__ float hbuf[NGH];
    __shared__ float logits[NE];

    if (tid < NC) pooled[tid] = g_pooled[b * NC + tid];
    __syncthreads();

    if (tid < NGH) {
        float a = bg1[tid];
        #pragma unroll
        for (int c = 0; c < NC; c++) a += pooled[c] * wg1[c * NGH + tid];
        hbuf[tid] = a > 0.f ? a : 0.f;
    }
    __syncthreads();

    if (tid < NE) {
        float a = bg2[tid];
        #pragma unroll
        for (int g = 0; g < NGH; g++) a += hbuf[g] * wg2[g * NE + tid];
        logits[tid] = a;
    }
    __syncthreads();

    if (tid == 0) {
        float m = -1e30f;
        #pragma unroll
        for (int e = 0; e < NE; e++) m = fmaxf(m, logits[e]);
        float p[NE], s = 0.f;
        #pragma unroll
        for (int e = 0; e < NE; e++) { p[e] = expf(logits[e] - m); s += p[e]; }
        float inv = 1.0f / s;
        #pragma unroll
        for (int e = 0; e < NE; e++) p[e] *= inv;
        int i1 = 0;
        #pragma unroll
        for (int e = 1; e < NE; e++) if (p[e] > p[i1]) i1 = e;
        int i2 = -1;
        #pragma unroll
        for (int e = 0; e < NE; e++) {
            if (e == i1) continue;
            if (i2 < 0 || p[e] > p[i2]) i2 = e;
        }
        float denom = p[i1] + p[i2] + 1e-8f;
        #pragma unroll
        for (int e = 0; e < NE; e++)
            g_probs[b][e] = (e == i1 || e == i2) ? p[e] / denom : 0.f;
    }
}

// ---------------------------------------------------------------------------
// Kernel 2: fold routing probs into per-batch conv weights + bias.
// ---------------------------------------------------------------------------
__global__ void combine_kernel(const float* __restrict__ w_exp,
                               const float* __restrict__ b_exp) {
    const int idx = blockIdx.x * blockDim.x + threadIdx.x;
    const int total = NB * NC * NC * 9;
    if (idx < total) {
        const int b = idx / (NC * NC * 9);
        const int r = idx - b * (NC * NC * 9);   // co*(NC*9) + ci*9 + tap
        const int co = r / (NC * 9);
        const int r2 = r - co * (NC * 9);        // ci*9 + tap
        float s = 0.f;
        #pragma unroll
        for (int e = 0; e < NE; e++)
            s += g_probs[b][e] * w_exp[((size_t)(e * NC + co) * NC) * 9 + r2];
        g_wcomb[idx] = s;
    }
    if (idx < NB * NC) {
        const int b = idx / NC, c = idx - b * NC;
        float s = 0.f;
        #pragma unroll
        for (int e = 0; e < NE; e++) s += g_probs[b][e] * b_exp[e * NC + c];
        g_bcomb[b][c] = s;
    }
}

// ---------------------------------------------------------------------------
// Kernel 3: per-batch 3x3 SAME conv, fused bias + residual, f32x2 FMA.
// Tile 32(w) x 64(h). Block 256 = 8(px) x 32(py); each thread: 4(dx) x 2(dy)
// outputs for 8 c_out. ky loop is OUTERMOST with a rolling 2-row register
// window so only 10 packed input regs are live (fits 128-reg budget; R4
// kept 20 live and spilled).
// Grid: (8 tiles, 8 cog, 16 b).
// ---------------------------------------------------------------------------
#define TCI 4
#define TCO 8

struct RowP { ull E0, E1, E2, O0, O1; };

__device__ __forceinline__ RowP load_row(const float* row) {
    RowP r;
    const float4 a = *(const float4*)row;
    const float2 b = *(const float2*)(row + 4);
    PACK2(r.E0, a.x, a.y);
    PACK2(r.E1, a.z, a.w);
    PACK2(r.E2, b.x, b.y);
    PACK2(r.O0, a.y, a.z);
    PACK2(r.O1, a.w, b.x);
    return r;
}

__global__ __launch_bounds__(256, 2)
void conv_kernel(const float* __restrict__ x, float* __restrict__ out) {
    const int tile = blockIdx.x;          // 0..7: 4 x-tiles, 2 y-tiles
    const int cog  = blockIdx.y;          // 0..7
    const int b    = blockIdx.z;          // 0..15
    const int tx = tile & 3, tyi = tile >> 2;
    const int X0 = tx * 32, Y0 = tyi * 64;

    const int tid = threadIdx.x;
    const int px = tid & 7, py = tid >> 3;   // 8 x 32

    __shared__ float  in_s[TCI][66][36];     // 66 rows (64+2 halo), stride 144B
    __shared__ float2 w2_s[TCO][TCI][9];     // duplicated weights {w,w}

    ull acc2[TCO][2][2];                     // [co][dy][pair]
    #pragma unroll
    for (int co = 0; co < TCO; co++)
        #pragma unroll
        for (int dy = 0; dy < 2; dy++) {
            acc2[co][dy][0] = 0ull;
            acc2[co][dy][1] = 0ull;
        }

    const float* xb = x + (size_t)b * NC * NH * NW;
    const float* wb = g_wcomb + (size_t)b * NC * NC * 9;

    for (int cb = 0; cb < NC / TCI; cb++) {
        __syncthreads();
        // stage input: TCI channels x 66x34 (zero-padded halo)
        for (int i = tid; i < TCI * 66 * 34; i += 256) {
            const int ci = i / (66 * 34);
            const int rr = i - ci * (66 * 34);
            const int iy = rr / 34, ix = rr - iy * 34;
            const int gy = Y0 - 1 + iy;
            const int gx = X0 - 1 + ix;
            float v = 0.f;
            if (gy >= 0 && gy < NH && gx >= 0 && gx < NW)
                v = xb[((size_t)(cb * TCI + ci) * NH + gy) * NW + gx];
            in_s[ci][iy][ix] = v;
        }
        // stage duplicated weights: 288 elements (grid-stride; > 256 threads)
        for (int i = tid; i < TCO * TCI * 9; i += 256) {
            const int co = i / (TCI * 9);
            const int r  = i - co * (TCI * 9);
            const int ci = r / 9, tap = r - ci * 9;
            const float v =
                wb[((size_t)(cog * TCO + co) * NC + cb * TCI + ci) * 9 + tap];
            w2_s[co][ci][tap] = make_float2(v, v);
        }
        __syncthreads();

        #pragma unroll 1
        for (int ci = 0; ci < TCI; ci++) {
            const float* rbase = &in_s[ci][py * 2][px * 4];
            RowP cur = load_row(rbase);
            RowP nxt = load_row(rbase + 36);

            #pragma unroll
            for (int ky = 0; ky < 3; ky++) {
                #pragma unroll
                for (int co = 0; co < TCO; co++) {
                    const ull* wp = (const ull*)&w2_s[co][ci][ky * 3];
                    const ull w0 = wp[0];
                    FMA2(acc2[co][0][0], cur.E0, w0);
                    FMA2(acc2[co][0][1], cur.E1, w0);
                    FMA2(acc2[co][1][0], nxt.E0, w0);
                    FMA2(acc2[co][1][1], nxt.E1, w0);
                    const ull w1 = wp[1];
                    FMA2(acc2[co][0][0], cur.O0, w1);
                    FMA2(acc2[co][0][1], cur.O1, w1);
                    FMA2(acc2[co][1][0], nxt.O0, w1);
                    FMA2(acc2[co][1][1], nxt.O1, w1);
                    const ull w2 = wp[2];
                    FMA2(acc2[co][0][0], cur.E1, w2);
                    FMA2(acc2[co][0][1], cur.E2, w2);
                    FMA2(acc2[co][1][0], nxt.E1, w2);
                    FMA2(acc2[co][1][1], nxt.E2, w2);
                }
                if (ky < 2) {
                    cur = nxt;
                    nxt = load_row(rbase + 36 * (ky + 2));
                }
            }
        }
    }

    // epilogue: bias + residual, float4 stores
    const int oy0 = Y0 + py * 2;
    const int ox0 = X0 + px * 4;
    #pragma unroll
    for (int co = 0; co < TCO; co++) {
        const int cg = cog * TCO + co;
        const float bias = g_bcomb[b][cg];
        #pragma unroll
        for (int dy = 0; dy < 2; dy++) {
            const size_t o = ((size_t)(b * NC + cg) * NH + (oy0 + dy)) * NW + ox0;
            float a0, a1, a2, a3;
            UNPACK2(a0, a1, acc2[co][dy][0]);
            UNPACK2(a2, a3, acc2[co][dy][1]);
            const float4 res = *(const float4*)(x + o);
            float4 v;
            v.x = a0 + bias + res.x;
            v.y = a1 + bias + res.y;
            v.z = a2 + bias + res.z;
            v.w = a3 + bias + res.w;
            *(float4*)(out + o) = v;
        }
    }
}

extern "C" void kernel_launch(void* const* d_in, const int* in_sizes, int n_in,
                              void* d_out, int out_size) {
    const float* x     = (const float*)d_in[0];
    const float* wg1   = (const float*)d_in[1];
    const float* bg1   = (const float*)d_in[2];
    const float* wg2   = (const float*)d_in[3];
    const float* bg2   = (const float*)d_in[4];
    const float* w_exp = (const float*)d_in[5];
    const float* b_exp = (const float*)d_in[6];
    float* out = (float*)d_out;

    pool_kernel<<<NB * NC, 256>>>(x);
    gate_kernel<<<NB, 64>>>(wg1, bg1, wg2, bg2);

    const int total = NB * NC * NC * 9;
    combine_kernel<<<(total + 255) / 256, 256>>>(w_exp, b_exp);

    dim3 grid(8, NC / TCO, NB);
    conv_kernel<<<grid, 256>>>(x, out);
}